// round 6
// baseline (speedup 1.0000x reference)
#include <cuda_runtime.h>
#include <math.h>
#include <stdint.h>

#define BATCH   4096
#define D_MODEL 1024
#define NT      64
#define RANK    8
#define NR      512

// Scratch (device globals: no allocation allowed)
__device__ float g_Y[(size_t)BATCH * NR];     // gated Vx, pre-rounded to tf32 bits
__device__ float g_Wt[(size_t)D_MODEL * NR];  // U transposed, pre-rounded to tf32 bits
__device__ float g_pre[(size_t)BATCH * NT];   // split-K accumulator (zero-init, self-reset)

__device__ __forceinline__ uint32_t f2tf32(float f) {
    uint32_t u;
    asm("cvt.rna.tf32.f32 %0, %1;" : "=r"(u) : "f"(f));
    return u;
}

__device__ __forceinline__ void mma_tf32(float c[4], const uint32_t a[4], const uint32_t b[2]) {
    asm volatile(
        "mma.sync.aligned.m16n8k8.row.col.f32.tf32.tf32.f32 "
        "{%0,%1,%2,%3}, {%4,%5,%6,%7}, {%8,%9}, {%0,%1,%2,%3};"
        : "+f"(c[0]), "+f"(c[1]), "+f"(c[2]), "+f"(c[3])
        : "r"(a[0]), "r"(a[1]), "r"(a[2]), "r"(a[3]), "r"(b[0]), "r"(b[1]));
}

__device__ __forceinline__ void cp16(void* smem_dst, const void* gmem_src) {
    uint32_t sa = (uint32_t)__cvta_generic_to_shared(smem_dst);
    asm volatile("cp.async.cg.shared.global [%0], [%1], 16;\n" :: "r"(sa), "l"(gmem_src));
}

// ---------------------------------------------------------------------------
// tf32 NT GEMM, 3-stage cp.async pipeline: C[M,N] = A[M,K] @ B[N,K]^T
// 256 threads, warps 2x4, BK=32.
// MODE 1: v = round_tf32(acc * gate[row][col/8]) -> g_Y
// MODE 2: plain, A := g_Y, B := g_Wt -> C       (CVT=false: inputs pre-rounded)
// MODE 3: split-K partial: atomicAdd into g_pre
// ---------------------------------------------------------------------------
template <int BM, int BN, int MODE, bool CVT>
__global__ __launch_bounds__(256, 2)
void tc_gemm(const float* __restrict__ Ag, const float* __restrict__ Bg,
             float* __restrict__ Cg, int lda, int ldb, int Kloop, int ldc,
             const float* __restrict__ gate)
{
    constexpr int BK = 32;
    constexpr int WY = 2, WX = 4;
    constexpr int WM = BM / WY;          // 64 or 32
    constexpr int WN = BN / WX;          // 32 or 16
    constexpr int MI = WM / 16;
    constexpr int NI = WN / 8;
    constexpr int RW = BK + 4;           // smem row words
    constexpr int SW = (BM + BN) * RW;   // words per stage
    constexpr int ACH = BM * 8 / 256;    // 16B chunks per thread (A)
    constexpr int BCH = BN * 8 / 256;

    extern __shared__ uint32_t smu[];

    const int tid  = threadIdx.x;
    const int wid  = tid >> 5;
    const int lane = tid & 31;
    const int wy   = wid / WX;
    const int wx   = wid % WX;
    const int lq   = lane >> 2;
    const int lr   = lane & 3;
    const int row0 = blockIdx.y * BM;
    const int col0 = (MODE == 3) ? 0 : blockIdx.x * BN;
    const int koff = (MODE == 3) ? blockIdx.x * Kloop : 0;

    const float* A = (MODE == 2) ? g_Y  : Ag;
    const float* B = (MODE == 2) ? g_Wt : Bg;

    float acc[MI][NI][4];
#pragma unroll
    for (int mi = 0; mi < MI; mi++)
#pragma unroll
        for (int ni = 0; ni < NI; ni++)
#pragma unroll
            for (int j = 0; j < 4; j++) acc[mi][ni][j] = 0.0f;

    auto issue = [&](int t) {
        const int s = t % 3;
        uint32_t* as = smu + s * SW;
        uint32_t* bs = as + BM * RW;
        const int k0 = koff + t * BK;
#pragma unroll
        for (int j = 0; j < ACH; j++) {
            int ch = tid + j * 256;
            int r = ch >> 3, c4 = ch & 7;
            cp16(&as[r * RW + c4 * 4], &A[(size_t)(row0 + r) * lda + k0 + c4 * 4]);
        }
#pragma unroll
        for (int j = 0; j < BCH; j++) {
            int ch = tid + j * 256;
            int r = ch >> 3, c4 = ch & 7;
            cp16(&bs[r * RW + c4 * 4], &B[(size_t)(col0 + r) * ldb + k0 + c4 * 4]);
        }
        asm volatile("cp.async.commit_group;\n");
    };

    auto compute = [&](int s) {
        const uint32_t* as = smu + s * SW;
        const uint32_t* bs = as + BM * RW;
#pragma unroll
        for (int kk = 0; kk < BK; kk += 8) {
            uint32_t af[MI][4], bf[NI][2];
#pragma unroll
            for (int mi = 0; mi < MI; mi++) {
                int r = wy * WM + mi * 16 + lq;
                uint32_t r0 = as[r * RW + kk + lr];
                uint32_t r1 = as[(r + 8) * RW + kk + lr];
                uint32_t r2 = as[r * RW + kk + lr + 4];
                uint32_t r3 = as[(r + 8) * RW + kk + lr + 4];
                if (CVT) {
                    r0 = f2tf32(__uint_as_float(r0));
                    r1 = f2tf32(__uint_as_float(r1));
                    r2 = f2tf32(__uint_as_float(r2));
                    r3 = f2tf32(__uint_as_float(r3));
                }
                af[mi][0] = r0; af[mi][1] = r1; af[mi][2] = r2; af[mi][3] = r3;
            }
#pragma unroll
            for (int ni = 0; ni < NI; ni++) {
                int c = wx * WN + ni * 8 + lq;
                uint32_t b0 = bs[c * RW + kk + lr];
                uint32_t b1 = bs[c * RW + kk + lr + 4];
                if (CVT) {
                    b0 = f2tf32(__uint_as_float(b0));
                    b1 = f2tf32(__uint_as_float(b1));
                }
                bf[ni][0] = b0; bf[ni][1] = b1;
            }
#pragma unroll
            for (int mi = 0; mi < MI; mi++)
#pragma unroll
                for (int ni = 0; ni < NI; ni++)
                    mma_tf32(acc[mi][ni], af[mi], bf[ni]);
        }
    };

    const int T = Kloop / BK;   // >= 4 in all phases

    issue(0);
    issue(1);
    asm volatile("cp.async.wait_group 1;\n");
    __syncthreads();

    for (int t = 0; t < T; t++) {
        if (t + 2 < T) issue(t + 2);
        compute(t % 3);
        if (t + 1 < T) {
            if (t + 2 < T) asm volatile("cp.async.wait_group 1;\n");
            else           asm volatile("cp.async.wait_group 0;\n");
            __syncthreads();
        }
    }

    // ---- epilogue ----
#pragma unroll
    for (int mi = 0; mi < MI; mi++) {
        int r0 = row0 + wy * WM + mi * 16 + lq;
#pragma unroll
        for (int ni = 0; ni < NI; ni++) {
            int c = col0 + wx * WN + ni * 8 + 2 * lr;
            float v0 = acc[mi][ni][0], v1 = acc[mi][ni][1];
            float v2 = acc[mi][ni][2], v3 = acc[mi][ni][3];
            if constexpr (MODE == 1) {
                int gc = (col0 + wx * WN + ni * 8) >> 3;
                float g0 = gate[(size_t)r0 * NT + gc];
                float g1 = gate[(size_t)(r0 + 8) * NT + gc];
                float2 o0, o1;   // store pre-rounded tf32 bits for phase 3
                o0.x = __uint_as_float(f2tf32(v0 * g0));
                o0.y = __uint_as_float(f2tf32(v1 * g0));
                o1.x = __uint_as_float(f2tf32(v2 * g1));
                o1.y = __uint_as_float(f2tf32(v3 * g1));
                *(float2*)&g_Y[(size_t)r0 * ldc + c]       = o0;
                *(float2*)&g_Y[(size_t)(r0 + 8) * ldc + c] = o1;
            } else if constexpr (MODE == 2) {
                *(float2*)&Cg[(size_t)r0 * ldc + c]       = make_float2(v0, v1);
                *(float2*)&Cg[(size_t)(r0 + 8) * ldc + c] = make_float2(v2, v3);
            } else {
                atomicAdd(&g_pre[(size_t)r0 * NT + c], v0);
                atomicAdd(&g_pre[(size_t)r0 * NT + c + 1], v1);
                atomicAdd(&g_pre[(size_t)(r0 + 8) * NT + c], v2);
                atomicAdd(&g_pre[(size_t)(r0 + 8) * NT + c + 1], v3);
            }
        }
    }
}

// gate = relu(pre - bias); reset pre for next replay
__global__ void gate_relu(const float* __restrict__ bias, float* __restrict__ gate)
{
    int i = blockIdx.x * 256 + threadIdx.x;
    int c = (i * 4) & (NT - 1);
    float4 p = *(float4*)&g_pre[(size_t)i * 4];
    float4 b = *(const float4*)&bias[c];
    float4 o;
    float v0 = p.x - b.x, v1 = p.y - b.y, v2 = p.z - b.z, v3 = p.w - b.w;
    o.x = v0 > 0.f ? v0 : 0.f;  o.y = v1 > 0.f ? v1 : 0.f;
    o.z = v2 > 0.f ? v2 : 0.f;  o.w = v3 > 0.f ? v3 : 0.f;
    *(float4*)&gate[(size_t)i * 4] = o;
    *(float4*)&g_pre[(size_t)i * 4] = make_float4(0.f, 0.f, 0.f, 0.f);
}

// prep: blocks [0,2048) transpose U -> g_Wt (rounded); blocks [2048,2112) fro norms
__global__ void prep(const float* __restrict__ U, const float* __restrict__ V,
                     float* __restrict__ fro)
{
    __shared__ float ssu[256];
    __shared__ float ssv[256];
    if (blockIdx.x < 2048) {
        int idx = blockIdx.x * 256 + threadIdx.x;
        int d = idx >> 9;
        int k = idx & (NR - 1);
        float v = U[(size_t)(k >> 3) * (D_MODEL * RANK) + (size_t)d * RANK + (k & 7)];
        g_Wt[idx] = __uint_as_float(f2tf32(v));
    } else {
        int n = blockIdx.x - 2048;
        float su = 0.0f, sv = 0.0f;
        for (int i = threadIdx.x; i < D_MODEL * RANK; i += 256) {
            float u = U[(size_t)n * (D_MODEL * RANK) + i];
            float v = V[(size_t)n * (D_MODEL * RANK) + i];
            su += u * u;
            sv += v * v;
        }
        ssu[threadIdx.x] = su;
        ssv[threadIdx.x] = sv;
        __syncthreads();
        for (int s = 128; s > 0; s >>= 1) {
            if (threadIdx.x < s) {
                ssu[threadIdx.x] += ssu[threadIdx.x + s];
                ssv[threadIdx.x] += ssv[threadIdx.x + s];
            }
            __syncthreads();
        }
        if (threadIdx.x == 0)
            fro[n] = sqrtf(ssu[0]) * sqrtf(ssv[0]) * rsqrtf((float)(D_MODEL * RANK));
    }
}

extern "C" void kernel_launch(void* const* d_in, const int* in_sizes, int n_in,
                              void* d_out, int out_size)
{
    const float* x    = (const float*)d_in[0];
    const float* V    = (const float*)d_in[1];
    const float* U    = (const float*)d_in[2];
    const float* enc  = (const float*)d_in[3];
    const float* bias = (const float*)d_in[4];

    float* out  = (float*)d_out;
    float* gate = out + (size_t)BATCH * D_MODEL;
    float* fro  = gate + (size_t)BATCH * NT;

    constexpr int SM_P1 = 3 * (128 + 64) * 36 * 4;    // 82944
    constexpr int SM_P2 = 3 * (64 + 128) * 36 * 4;    // 82944
    constexpr int SM_P3 = 3 * (128 + 128) * 36 * 4;   // 110592

    cudaFuncSetAttribute(tc_gemm<128, 64, 3, true>,
                         cudaFuncAttributeMaxDynamicSharedMemorySize, SM_P1);
    cudaFuncSetAttribute(tc_gemm<64, 128, 1, true>,
                         cudaFuncAttributeMaxDynamicSharedMemorySize, SM_P2);
    cudaFuncSetAttribute(tc_gemm<128, 128, 2, false>,
                         cudaFuncAttributeMaxDynamicSharedMemorySize, SM_P3);

    // Phase 1 (split-K x8): g_pre += x @ enc^T   [4096 x 64]  grid 256
    tc_gemm<128, 64, 3, true><<<dim3(8, BATCH / 128), 256, SM_P1>>>(
        x, enc, nullptr, D_MODEL, D_MODEL, 128, 0, nullptr);

    // prep: transpose U (rounded) + Frobenius norms
    prep<<<2048 + NT, 256>>>(U, V, fro);

    // Phase 1b: gate = relu(pre - bias), reset pre
    gate_relu<<<BATCH * NT / 4 / 256, 256>>>(bias, gate);

    // Phase 2: g_Y = round_tf32((x @ V^T) * gate)  [4096 x 512]  grid 256
    tc_gemm<64, 128, 1, true><<<dim3(NR / 128, BATCH / 64), 256, SM_P2>>>(
        x, V, nullptr, D_MODEL, D_MODEL, D_MODEL, NR, gate);

    // Phase 3: out = g_Y @ g_Wt^T   [4096 x 1024]  grid 256
    tc_gemm<128, 128, 2, false><<<dim3(D_MODEL / 128, BATCH / 128), 256, SM_P3>>>(
        nullptr, nullptr, out, NR, NR, NR, D_MODEL, nullptr);
}

// round 7
// speedup vs baseline: 1.0427x; 1.0427x over previous
#include <cuda_runtime.h>
#include <math.h>
#include <stdint.h>

#define BATCH   4096
#define D_MODEL 1024
#define NT      64
#define RANK    8
#define NR      512

// Scratch (device globals; zero-init where semantics need it)
__device__ float g_Xr[(size_t)BATCH * D_MODEL];   // x rounded to tf32 bits
__device__ float g_Vr[(size_t)NR * D_MODEL];      // V rounded
__device__ float g_Er[(size_t)NT * D_MODEL];      // encoder rounded
__device__ float g_Y[(size_t)BATCH * NR];         // gated Vx, rounded
__device__ float g_Wt[(size_t)D_MODEL * NR];      // U^T, rounded
__device__ float g_pre[(size_t)BATCH * NT];       // split-K accumulator (self-reset)

__device__ __forceinline__ uint32_t f2tf32(float f) {
    uint32_t u;
    asm("cvt.rna.tf32.f32 %0, %1;" : "=r"(u) : "f"(f));
    return u;
}
__device__ __forceinline__ float rnd(float f) { return __uint_as_float(f2tf32(f)); }

__device__ __forceinline__ void mma_tf32(float c[4], const uint32_t a[4], const uint32_t b[2]) {
    asm volatile(
        "mma.sync.aligned.m16n8k8.row.col.f32.tf32.tf32.f32 "
        "{%0,%1,%2,%3}, {%4,%5,%6,%7}, {%8,%9}, {%0,%1,%2,%3};"
        : "+f"(c[0]), "+f"(c[1]), "+f"(c[2]), "+f"(c[3])
        : "r"(a[0]), "r"(a[1]), "r"(a[2]), "r"(a[3]), "r"(b[0]), "r"(b[1]));
}

__device__ __forceinline__ void cp16(void* smem_dst, const void* gmem_src) {
    uint32_t sa = (uint32_t)__cvta_generic_to_shared(smem_dst);
    asm volatile("cp.async.cg.shared.global [%0], [%1], 16;\n" :: "r"(sa), "l"(gmem_src));
}

// ---------------------------------------------------------------------------
// tf32 NT GEMM, 3-stage cp.async, warp tile 64x32 (or 64x16), NO cvt anywhere:
// all inputs pre-rounded to tf32 bit patterns.
// MODE 1: v = round(acc * gate[row][col/8]) -> g_Y   (A=g_Xr, B=g_Vr)
// MODE 2: plain -> C                                  (A=g_Y,  B=g_Wt)
// MODE 3: split-K partial -> atomicAdd g_pre          (A=g_Xr, B=g_Er)
// ---------------------------------------------------------------------------
template <int BM, int BN, int WY, int WX, int MODE>
__global__ __launch_bounds__(WY * WX * 32, 2)
void tc_gemm(float* __restrict__ Cg, int lda, int ldb, int Kloop, int ldc,
             const float* __restrict__ gate)
{
    constexpr int BK = 32;
    constexpr int THREADS = WY * WX * 32;
    constexpr int WM = BM / WY;          // 64
    constexpr int WN = BN / WX;          // 32 or 16
    constexpr int MI = WM / 16;          // 4
    constexpr int NI = WN / 8;           // 4 or 2
    constexpr int RW = BK + 4;
    constexpr int SW = (BM + BN) * RW;
    constexpr int ACH = BM * 8 / THREADS;
    constexpr int BCH = BN * 8 / THREADS;

    extern __shared__ uint32_t smu[];

    const int tid  = threadIdx.x;
    const int wid  = tid >> 5;
    const int lane = tid & 31;
    const int wy   = wid / WX;
    const int wx   = wid % WX;
    const int lq   = lane >> 2;
    const int lr   = lane & 3;
    const int row0 = blockIdx.y * BM;
    const int col0 = (MODE == 3) ? 0 : blockIdx.x * BN;
    const int koff = (MODE == 3) ? blockIdx.x * Kloop : 0;

    const float* A = (MODE == 2) ? g_Y  : g_Xr;
    const float* B = (MODE == 1) ? g_Vr : ((MODE == 2) ? g_Wt : g_Er);

    float acc[MI][NI][4];
#pragma unroll
    for (int mi = 0; mi < MI; mi++)
#pragma unroll
        for (int ni = 0; ni < NI; ni++)
#pragma unroll
            for (int j = 0; j < 4; j++) acc[mi][ni][j] = 0.0f;

    auto issue = [&](int t) {
        const int s = t % 3;
        uint32_t* as = smu + s * SW;
        uint32_t* bs = as + BM * RW;
        const int k0 = koff + t * BK;
#pragma unroll
        for (int j = 0; j < ACH; j++) {
            int ch = tid + j * THREADS;
            int r = ch >> 3, c4 = ch & 7;
            cp16(&as[r * RW + c4 * 4], &A[(size_t)(row0 + r) * lda + k0 + c4 * 4]);
        }
#pragma unroll
        for (int j = 0; j < BCH; j++) {
            int ch = tid + j * THREADS;
            int r = ch >> 3, c4 = ch & 7;
            cp16(&bs[r * RW + c4 * 4], &B[(size_t)(col0 + r) * ldb + k0 + c4 * 4]);
        }
        asm volatile("cp.async.commit_group;\n");
    };

    auto compute = [&](int s) {
        const uint32_t* as = smu + s * SW;
        const uint32_t* bs = as + BM * RW;
#pragma unroll
        for (int kk = 0; kk < BK; kk += 8) {
            uint32_t af[MI][4], bf[NI][2];
#pragma unroll
            for (int mi = 0; mi < MI; mi++) {
                int r = wy * WM + mi * 16 + lq;
                af[mi][0] = as[r * RW + kk + lr];
                af[mi][1] = as[(r + 8) * RW + kk + lr];
                af[mi][2] = as[r * RW + kk + lr + 4];
                af[mi][3] = as[(r + 8) * RW + kk + lr + 4];
            }
#pragma unroll
            for (int ni = 0; ni < NI; ni++) {
                int c = wx * WN + ni * 8 + lq;
                bf[ni][0] = bs[c * RW + kk + lr];
                bf[ni][1] = bs[c * RW + kk + lr + 4];
            }
#pragma unroll
            for (int mi = 0; mi < MI; mi++)
#pragma unroll
                for (int ni = 0; ni < NI; ni++)
                    mma_tf32(acc[mi][ni], af[mi], bf[ni]);
        }
    };

    const int T = Kloop / BK;   // >= 4 everywhere

    issue(0);
    issue(1);
    asm volatile("cp.async.wait_group 1;\n");
    __syncthreads();

    for (int t = 0; t < T; t++) {
        if (t + 2 < T) issue(t + 2);
        compute(t % 3);
        if (t + 1 < T) {
            if (t + 2 < T) asm volatile("cp.async.wait_group 1;\n");
            else           asm volatile("cp.async.wait_group 0;\n");
            __syncthreads();
        }
    }

    // ---- epilogue ----
#pragma unroll
    for (int mi = 0; mi < MI; mi++) {
        int r0 = row0 + wy * WM + mi * 16 + lq;
#pragma unroll
        for (int ni = 0; ni < NI; ni++) {
            int c = col0 + wx * WN + ni * 8 + 2 * lr;
            float v0 = acc[mi][ni][0], v1 = acc[mi][ni][1];
            float v2 = acc[mi][ni][2], v3 = acc[mi][ni][3];
            if constexpr (MODE == 1) {
                int gc = (col0 + wx * WN + ni * 8) >> 3;
                float g0 = gate[(size_t)r0 * NT + gc];
                float g1 = gate[(size_t)(r0 + 8) * NT + gc];
                float2 o0, o1;   // pre-rounded for phase 3
                o0.x = rnd(v0 * g0);  o0.y = rnd(v1 * g0);
                o1.x = rnd(v2 * g1);  o1.y = rnd(v3 * g1);
                *(float2*)&g_Y[(size_t)r0 * ldc + c]       = o0;
                *(float2*)&g_Y[(size_t)(r0 + 8) * ldc + c] = o1;
            } else if constexpr (MODE == 2) {
                *(float2*)&Cg[(size_t)r0 * ldc + c]       = make_float2(v0, v1);
                *(float2*)&Cg[(size_t)(r0 + 8) * ldc + c] = make_float2(v2, v3);
            } else {
                atomicAdd(&g_pre[(size_t)r0 * NT + c], v0);
                atomicAdd(&g_pre[(size_t)r0 * NT + c + 1], v1);
                atomicAdd(&g_pre[(size_t)(r0 + 8) * NT + c], v2);
                atomicAdd(&g_pre[(size_t)(r0 + 8) * NT + c + 1], v3);
            }
        }
    }
}

// ---------------------------------------------------------------------------
// prep: round x/V/enc to tf32 bits, transpose+round U, Frobenius norms
// ---------------------------------------------------------------------------
#define PB_X   (BATCH * D_MODEL / 4 / 256)          /* 4096 */
#define PB_V   (NR * D_MODEL / 4 / 256)             /* 512  */
#define PB_E   (NT * D_MODEL / 4 / 256)             /* 64   */
#define PB_W   (D_MODEL * NR / 256)                 /* 2048 */
__global__ void prep(const float* __restrict__ x, const float* __restrict__ V,
                     const float* __restrict__ U, const float* __restrict__ enc,
                     float* __restrict__ fro)
{
    __shared__ float ssu[256];
    __shared__ float ssv[256];
    int b = blockIdx.x;
    if (b < PB_X) {
        int i = b * 256 + threadIdx.x;
        float4 v = *(const float4*)&x[(size_t)i * 4];
        float4 o = make_float4(rnd(v.x), rnd(v.y), rnd(v.z), rnd(v.w));
        *(float4*)&g_Xr[(size_t)i * 4] = o;
    } else if (b < PB_X + PB_V) {
        int i = (b - PB_X) * 256 + threadIdx.x;
        float4 v = *(const float4*)&V[(size_t)i * 4];
        float4 o = make_float4(rnd(v.x), rnd(v.y), rnd(v.z), rnd(v.w));
        *(float4*)&g_Vr[(size_t)i * 4] = o;
    } else if (b < PB_X + PB_V + PB_E) {
        int i = (b - PB_X - PB_V) * 256 + threadIdx.x;
        float4 v = *(const float4*)&enc[(size_t)i * 4];
        float4 o = make_float4(rnd(v.x), rnd(v.y), rnd(v.z), rnd(v.w));
        *(float4*)&g_Er[(size_t)i * 4] = o;
    } else if (b < PB_X + PB_V + PB_E + PB_W) {
        int idx = (b - PB_X - PB_V - PB_E) * 256 + threadIdx.x;
        int d = idx >> 9;
        int k = idx & (NR - 1);
        g_Wt[idx] = rnd(U[(size_t)(k >> 3) * (D_MODEL * RANK) + (size_t)d * RANK + (k & 7)]);
    } else {
        int n = b - PB_X - PB_V - PB_E - PB_W;
        float su = 0.0f, sv = 0.0f;
        for (int i = threadIdx.x; i < D_MODEL * RANK; i += 256) {
            float u = U[(size_t)n * (D_MODEL * RANK) + i];
            float v = V[(size_t)n * (D_MODEL * RANK) + i];
            su += u * u;
            sv += v * v;
        }
        ssu[threadIdx.x] = su;
        ssv[threadIdx.x] = sv;
        __syncthreads();
        for (int s = 128; s > 0; s >>= 1) {
            if (threadIdx.x < s) {
                ssu[threadIdx.x] += ssu[threadIdx.x + s];
                ssv[threadIdx.x] += ssv[threadIdx.x + s];
            }
            __syncthreads();
        }
        if (threadIdx.x == 0)
            fro[n] = sqrtf(ssu[0]) * sqrtf(ssv[0]) * rsqrtf((float)(D_MODEL * RANK));
    }
}

// gate = relu(pre - bias); reset pre for next replay
__global__ void gate_relu(const float* __restrict__ bias, float* __restrict__ gate)
{
    int i = blockIdx.x * 256 + threadIdx.x;
    int c = (i * 4) & (NT - 1);
    float4 p = *(float4*)&g_pre[(size_t)i * 4];
    float4 b = *(const float4*)&bias[c];
    float4 o;
    float v0 = p.x - b.x, v1 = p.y - b.y, v2 = p.z - b.z, v3 = p.w - b.w;
    o.x = v0 > 0.f ? v0 : 0.f;  o.y = v1 > 0.f ? v1 : 0.f;
    o.z = v2 > 0.f ? v2 : 0.f;  o.w = v3 > 0.f ? v3 : 0.f;
    *(float4*)&gate[(size_t)i * 4] = o;
    *(float4*)&g_pre[(size_t)i * 4] = make_float4(0.f, 0.f, 0.f, 0.f);
}

extern "C" void kernel_launch(void* const* d_in, const int* in_sizes, int n_in,
                              void* d_out, int out_size)
{
    const float* x    = (const float*)d_in[0];
    const float* V    = (const float*)d_in[1];
    const float* U    = (const float*)d_in[2];
    const float* enc  = (const float*)d_in[3];
    const float* bias = (const float*)d_in[4];

    float* out  = (float*)d_out;
    float* gate = out + (size_t)BATCH * D_MODEL;
    float* fro  = gate + (size_t)BATCH * NT;

    constexpr int SM_P1 = 3 * (64 + 64) * 36 * 4;     // 55296
    constexpr int SM_P2 = 3 * (64 + 128) * 36 * 4;    // 82944
    constexpr int SM_P3 = 3 * (128 + 128) * 36 * 4;   // 110592

    cudaFuncSetAttribute(tc_gemm<64, 64, 1, 4, 3>,
                         cudaFuncAttributeMaxDynamicSharedMemorySize, SM_P1);
    cudaFuncSetAttribute(tc_gemm<64, 128, 1, 4, 1>,
                         cudaFuncAttributeMaxDynamicSharedMemorySize, SM_P2);
    cudaFuncSetAttribute(tc_gemm<128, 128, 2, 4, 2>,
                         cudaFuncAttributeMaxDynamicSharedMemorySize, SM_P3);

    // prep: round x/V/enc, build g_Wt, fro norms
    prep<<<PB_X + PB_V + PB_E + PB_W + NT, 256>>>(x, V, U, enc, fro);

    // Phase 1 (split-K x8): g_pre += x @ enc^T   [4096 x 64]  grid 512
    tc_gemm<64, 64, 1, 4, 3><<<dim3(8, BATCH / 64), 128, SM_P1>>>(
        nullptr, D_MODEL, D_MODEL, 128, 0, nullptr);

    // Phase 1b: gate = relu(pre - bias), reset pre
    gate_relu<<<BATCH * NT / 4 / 256, 256>>>(bias, gate);

    // Phase 2: g_Y = round((x @ V^T) * gate)  [4096 x 512]  grid 256
    tc_gemm<64, 128, 1, 4, 1><<<dim3(NR / 128, BATCH / 64), 128, SM_P2>>>(
        nullptr, D_MODEL, D_MODEL, D_MODEL, NR, gate);

    // Phase 3: out = g_Y @ g_Wt^T   [4096 x 1024]  grid 256
    tc_gemm<128, 128, 2, 4, 2><<<dim3(D_MODEL / 128, BATCH / 128), 256, SM_P3>>>(
        out, NR, NR, NR, D_MODEL, nullptr);
}